// round 3
// baseline (speedup 1.0000x reference)
#include <cuda_runtime.h>

// ---------------------------------------------------------------------------
// RelationMessagePassing on GB300 (sm_103a) — round 2: fix idx dtype (int32,
// JAX x64-disabled downgrades int64 -> int32), fp32x2 scalar pipeline.
//
// Phases (all graph-capturable kernel launches on the default stream):
//  K0: init expsum = 1e-16, g_maxoff = -inf
//  K1..K3: per-relation fused 2-layer MLP over gathered tuples.
//          writes o to __device__ scratch, block-reduces max -> atomicMax
//  K4..K6: per-relation exp(8*(o-max)) scatter-add into expsum
//  K7: update MLP: cat([log(expsum)/8+max, node_states]) -> relu -> out
// ---------------------------------------------------------------------------

#define NNODES 200000
#define HDIM 64

// scratch: o for all relations: 300000*128 + 300000*128 + 200000*192 = 115.2M floats
__device__ float g_o[115200000];
__device__ float g_expsum[NNODES * HDIM];
__device__ float g_maxoff;

// -------------------- packed f32x2 helpers (sm_103a FFMA2) ------------------
__device__ __forceinline__ unsigned long long pack2(float lo, float hi) {
    unsigned long long r;
    asm("mov.b64 %0, {%1, %2};" : "=l"(r) : "f"(lo), "f"(hi));
    return r;
}
__device__ __forceinline__ void unpack2(unsigned long long v, float& lo, float& hi) {
    asm("mov.b64 {%0, %1}, %2;" : "=f"(lo), "=f"(hi) : "l"(v));
}
__device__ __forceinline__ unsigned long long fma2(unsigned long long a,
                                                   unsigned long long b,
                                                   unsigned long long c) {
    unsigned long long d;
    asm("fma.rn.f32x2 %0, %1, %2, %3;" : "=l"(d) : "l"(a), "l"(b), "l"(c));
    return d;
}

__device__ __forceinline__ void atomicMaxFloat(float* addr, float v) {
    // sign-aware float max via integer atomics
    if (v >= 0.0f) atomicMax((int*)addr, __float_as_int(v));
    else           atomicMin((unsigned int*)addr, __float_as_uint(v));
}

// ------------------------------- K0: init -----------------------------------
__global__ void k_init() {
    long long i = (long long)blockIdx.x * blockDim.x + threadIdx.x;
    if (i == 0) g_maxoff = -3.402823466e38f;
    long long n4 = (long long)NNODES * HDIM / 4;
    if (i < n4) {
        float4 v = make_float4(1e-16f, 1e-16f, 1e-16f, 1e-16f);
        ((float4*)g_expsum)[i] = v;
    }
}

// ----------------- K1..K3: per-relation fused MLP + max ---------------------
// CTA: MT=32 tuples, blockDim = D = AR*64 threads, thread j owns column j.
// smem: Wsm [D x (D+1)] transposed weights; xT [D x 34] input^T; hT [D x 34].
template <int AR>
__global__ void k_rel(const float* __restrict__ ns,
                      const int* __restrict__ idx,
                      const float* __restrict__ w1, const float* __restrict__ b1,
                      const float* __restrict__ w2, const float* __restrict__ b2,
                      long long o_off) {
    constexpr int D = AR * 64;
    constexpr int DP = D + 1;
    constexpr int MT = 32;
    constexpr int MTP = 34;  // even pad -> 8B-aligned packed rows
    constexpr int NW = D / 32;

    extern __shared__ float sm[];
    float* Wsm = sm;                 // D*DP floats
    float* xT  = sm + D * DP;        // D*MTP floats
    float* hT  = xT + D * MTP;       // D*MTP floats

    const int t0 = blockIdx.x * MT;
    const int j = threadIdx.x;
    const int wid = j >> 5, lane = j & 31;

    // 1) gather x rows into xT[k][m]  (k = p*64+f)
    for (int r = wid; r < MT * AR; r += NW) {
        int m = r / AR, p = r % AR;
        int node = idx[(t0 + m) * AR + p];
        float2 v = ((const float2*)(ns + (long long)node * 64))[lane];
        xT[(p * 64 + 2 * lane)     * MTP + m] = v.x;
        xT[(p * 64 + 2 * lane + 1) * MTP + m] = v.y;
    }

    // 2) stage W1 transposed: Wsm[k][jj] = w1[jj*D + k]
    for (int e = j; e < D * D; e += D) {
        int jj = e / D, kk = e % D;          // kk == j
        Wsm[kk * DP + jj] = w1[e];
    }
    __syncthreads();

    unsigned long long acc[MT / 2];

    // 3) GEMM1 + relu -> hT
    {
        float bj = b1[j];
        unsigned long long bp = pack2(bj, bj);
#pragma unroll
        for (int mm = 0; mm < MT / 2; mm++) acc[mm] = bp;
        for (int k = 0; k < D; k++) {
            float w = Wsm[k * DP + j];
            unsigned long long wp = pack2(w, w);
            const unsigned long long* xrow = (const unsigned long long*)(&xT[k * MTP]);
#pragma unroll
            for (int mm = 0; mm < MT / 2; mm++) acc[mm] = fma2(xrow[mm], wp, acc[mm]);
        }
#pragma unroll
        for (int mm = 0; mm < MT / 2; mm++) {
            float lo, hi; unpack2(acc[mm], lo, hi);
            hT[j * MTP + 2 * mm]     = fmaxf(lo, 0.0f);
            hT[j * MTP + 2 * mm + 1] = fmaxf(hi, 0.0f);
        }
    }
    __syncthreads();

    // 4) stage W2 transposed (overwrite Wsm)
    for (int e = j; e < D * D; e += D) {
        int jj = e / D, kk = e % D;
        Wsm[kk * DP + jj] = w2[e];
    }
    __syncthreads();

    // 5) GEMM2
    {
        float bj = b2[j];
        unsigned long long bp = pack2(bj, bj);
#pragma unroll
        for (int mm = 0; mm < MT / 2; mm++) acc[mm] = bp;
        for (int k = 0; k < D; k++) {
            float w = Wsm[k * DP + j];
            unsigned long long wp = pack2(w, w);
            const unsigned long long* hrow = (const unsigned long long*)(&hT[k * MTP]);
#pragma unroll
            for (int mm = 0; mm < MT / 2; mm++) acc[mm] = fma2(hrow[mm], wp, acc[mm]);
        }
    }

    // 6) write o scratch + max reduce
    float mymax = -3.402823466e38f;
    float* oscr = g_o + o_off;
#pragma unroll
    for (int mm = 0; mm < MT / 2; mm++) {
        float lo, hi; unpack2(acc[mm], lo, hi);
        oscr[(long long)(t0 + 2 * mm)     * D + j] = lo;
        oscr[(long long)(t0 + 2 * mm + 1) * D + j] = hi;
        mymax = fmaxf(mymax, fmaxf(lo, hi));
    }
#pragma unroll
    for (int s = 16; s > 0; s >>= 1)
        mymax = fmaxf(mymax, __shfl_xor_sync(0xffffffff, mymax, s));
    __shared__ float wmax[8];
    if (lane == 0) wmax[wid] = mymax;
    __syncthreads();
    if (j == 0) {
        float bm = wmax[0];
        for (int w = 1; w < NW; w++) bm = fmaxf(bm, wmax[w]);
        atomicMaxFloat(&g_maxoff, bm);
    }
}

// ----------------- K4..K6: exp + scatter-add --------------------------------
template <int AR>
__global__ void k_scatter(const int* __restrict__ idx, long long o_off, int T) {
    constexpr int D = AR * 64;
    long long e4 = (long long)blockIdx.x * blockDim.x + threadIdx.x;
    long long total4 = (long long)T * D / 4;
    if (e4 >= total4) return;
    float maxoff = g_maxoff;
    float4 v = ((const float4*)(g_o + o_off))[e4];
    long long e = e4 * 4;
    int t = (int)(e / D);
    int jj = (int)(e % D);
    int p = jj >> 6, f = jj & 63;
    int node = idx[t * AR + p];
    float* dst = g_expsum + (long long)node * 64 + f;
    atomicAdd(dst + 0, __expf(8.0f * (v.x - maxoff)));
    atomicAdd(dst + 1, __expf(8.0f * (v.y - maxoff)));
    atomicAdd(dst + 2, __expf(8.0f * (v.z - maxoff)));
    atomicAdd(dst + 3, __expf(8.0f * (v.w - maxoff)));
}

// --------------------------- K7: update MLP ---------------------------------
// cat = [msg(64) | ns(64)], D=128. GEMM1 128->128 + relu, GEMM2 128->64.
__global__ void k_update(const float* __restrict__ ns,
                         const float* __restrict__ w1, const float* __restrict__ b1,
                         const float* __restrict__ w2, const float* __restrict__ b2,
                         float* __restrict__ out) {
    constexpr int D = 128, DP = 129, MT = 32, MTP = 34;
    extern __shared__ float sm[];
    float* Wsm = sm;
    float* xT  = sm + D * DP;
    float* hT  = xT + D * MTP;

    const int n0 = blockIdx.x * MT;
    const int j = threadIdx.x;
    const int wid = j >> 5, lane = j & 31;
    const float maxoff = g_maxoff;

    // build cat^T
    for (int m = wid; m < MT; m += 4) {
        long long n = n0 + m;
        float2 ev = ((const float2*)(g_expsum + n * 64))[lane];
        xT[(2 * lane)     * MTP + m] = 0.125f * __logf(ev.x) + maxoff;
        xT[(2 * lane + 1) * MTP + m] = 0.125f * __logf(ev.y) + maxoff;
        float2 sv = ((const float2*)(ns + n * 64))[lane];
        xT[(64 + 2 * lane)     * MTP + m] = sv.x;
        xT[(64 + 2 * lane + 1) * MTP + m] = sv.y;
    }
    for (int e = j; e < D * D; e += D) {
        int jj = e / D, kk = e % D;
        Wsm[kk * DP + jj] = w1[e];
    }
    __syncthreads();

    unsigned long long acc[16];
    {
        float bj = b1[j];
        unsigned long long bp = pack2(bj, bj);
#pragma unroll
        for (int mm = 0; mm < 16; mm++) acc[mm] = bp;
        for (int k = 0; k < D; k++) {
            float w = Wsm[k * DP + j];
            unsigned long long wp = pack2(w, w);
            const unsigned long long* xrow = (const unsigned long long*)(&xT[k * MTP]);
#pragma unroll
            for (int mm = 0; mm < 16; mm++) acc[mm] = fma2(xrow[mm], wp, acc[mm]);
        }
#pragma unroll
        for (int mm = 0; mm < 16; mm++) {
            float lo, hi; unpack2(acc[mm], lo, hi);
            hT[j * MTP + 2 * mm]     = fmaxf(lo, 0.0f);
            hT[j * MTP + 2 * mm + 1] = fmaxf(hi, 0.0f);
        }
    }
    __syncthreads();

    // stage u_w2 (64 x 128), pitch 65
    for (int e = j; e < 64 * D; e += D) {
        int jj = e / D, kk = e % D;
        Wsm[kk * 65 + jj] = w2[e];
    }
    __syncthreads();

    // GEMM2: 64 output cols; threads split rows by half = j>>6
    {
        int jo = j & 63, half = j >> 6;
        float bj = b2[jo];
        unsigned long long bp = pack2(bj, bj);
        unsigned long long a2[8];
#pragma unroll
        for (int mm = 0; mm < 8; mm++) a2[mm] = bp;
        for (int k = 0; k < D; k++) {
            float w = Wsm[k * 65 + jo];
            unsigned long long wp = pack2(w, w);
            const unsigned long long* hrow =
                (const unsigned long long*)(&hT[k * MTP + half * 16]);
#pragma unroll
            for (int mm = 0; mm < 8; mm++) a2[mm] = fma2(hrow[mm], wp, a2[mm]);
        }
#pragma unroll
        for (int mm = 0; mm < 8; mm++) {
            float lo, hi; unpack2(a2[mm], lo, hi);
            out[(long long)(n0 + half * 16 + 2 * mm)     * 64 + jo] = lo;
            out[(long long)(n0 + half * 16 + 2 * mm + 1) * 64 + jo] = hi;
        }
    }
}

// ---------------------------------------------------------------------------
extern "C" void kernel_launch(void* const* d_in, const int* in_sizes, int n_in,
                              void* d_out, int out_size) {
    const float* ns   = (const float*)d_in[0];
    const int*   idx0 = (const int*)d_in[1];
    const int*   idx1 = (const int*)d_in[2];
    const int*   idx2 = (const int*)d_in[3];
    const float* r0w1 = (const float*)d_in[4];
    const float* r0b1 = (const float*)d_in[5];
    const float* r0w2 = (const float*)d_in[6];
    const float* r0b2 = (const float*)d_in[7];
    const float* r1w1 = (const float*)d_in[8];
    const float* r1b1 = (const float*)d_in[9];
    const float* r1w2 = (const float*)d_in[10];
    const float* r1b2 = (const float*)d_in[11];
    const float* r2w1 = (const float*)d_in[12];
    const float* r2b1 = (const float*)d_in[13];
    const float* r2w2 = (const float*)d_in[14];
    const float* r2b2 = (const float*)d_in[15];
    const float* uw1  = (const float*)d_in[16];
    const float* ub1  = (const float*)d_in[17];
    const float* uw2  = (const float*)d_in[18];
    const float* ub2  = (const float*)d_in[19];
    float* out = (float*)d_out;

    const int T01 = 300000, T2 = 200000;
    const long long OFF0 = 0, OFF1 = 38400000LL, OFF2 = 76800000LL;

    // dynamic smem sizes
    const int SM2 = (128 * 129 + 2 * 128 * 34) * 4;   // 100864 B
    const int SM3 = (192 * 193 + 2 * 192 * 34) * 4;   // 200448 B
    cudaFuncSetAttribute((const void*)k_rel<2>, cudaFuncAttributeMaxDynamicSharedMemorySize, SM2);
    cudaFuncSetAttribute((const void*)k_rel<3>, cudaFuncAttributeMaxDynamicSharedMemorySize, SM3);
    cudaFuncSetAttribute((const void*)k_update, cudaFuncAttributeMaxDynamicSharedMemorySize, SM2);

    // K0: init
    {
        long long n4 = (long long)NNODES * HDIM / 4;  // 3.2M
        int bl = 256;
        int gr = (int)((n4 + bl - 1) / bl);
        k_init<<<gr, bl>>>();
    }

    // K1..K3: relation MLPs
    k_rel<2><<<T01 / 32, 128, SM2>>>(ns, idx0, r0w1, r0b1, r0w2, r0b2, OFF0);
    k_rel<2><<<T01 / 32, 128, SM2>>>(ns, idx1, r1w1, r1b1, r1w2, r1b2, OFF1);
    k_rel<3><<<T2  / 32, 192, SM3>>>(ns, idx2, r2w1, r2b1, r2w2, r2b2, OFF2);

    // K4..K6: exp scatter
    {
        int bl = 256;
        long long n0 = (long long)T01 * 128 / 4;
        long long n2 = (long long)T2 * 192 / 4;
        k_scatter<2><<<(int)((n0 + bl - 1) / bl), bl>>>(idx0, OFF0, T01);
        k_scatter<2><<<(int)((n0 + bl - 1) / bl), bl>>>(idx1, OFF1, T01);
        k_scatter<3><<<(int)((n2 + bl - 1) / bl), bl>>>(idx2, OFF2, T2);
    }

    // K7: update
    k_update<<<NNODES / 32, 128, SM2>>>(ns, uw1, ub1, uw2, ub2, out);
}

// round 8
// speedup vs baseline: 3.3577x; 3.3577x over previous
#include <cuda_runtime.h>
#include <cuda_bf16.h>
#include <cstdint>

// ---------------------------------------------------------------------------
// RelationMessagePassing on GB300 (sm_103, no 'a' features) — round 5:
// warp-level mma.sync bf16 hi/lo split (3-term => ~fp32 accuracy), with the
// exp-scatter fused into the MLP epilogue (unshifted exp accumulation):
//   msg = (1/8)*log(1e-16*e^{8*max} + sum(exp(8*o)))  ==  reference LSE
//
//  K0: expsum = 0, g_maxoff = -inf
//  K1..K3: per-relation fused 2-layer MLP + exp + red.global.add.v4 scatter
//          + atomicMax of o into g_maxoff
//  K4: update MLP: cat([1/8*log(eps'+S), node_states]) -> relu -> out
// ---------------------------------------------------------------------------

#define NNODES 200000

__device__ float g_expsum[NNODES * 64];
__device__ float g_maxoff;

// ------------------------------ helpers ------------------------------------
__device__ __forceinline__ uint32_t smem_u32(const void* p) {
    uint32_t a;
    asm("{ .reg .u64 t; cvta.to.shared.u64 t, %1; cvt.u32.u64 %0, t; }"
        : "=r"(a) : "l"(p));
    return a;
}

// split fp32 pair -> bf16x2 hi word + bf16x2 residual word (elem0 in low half)
__device__ __forceinline__ void split_pair(float a, float b, uint32_t& hi, uint32_t& lo) {
    __nv_bfloat16 ha = __float2bfloat16(a), hb = __float2bfloat16(b);
    __nv_bfloat162 hp = __halves2bfloat162(ha, hb);
    hi = *reinterpret_cast<uint32_t*>(&hp);
    float ra = a - __bfloat162float(ha);
    float rb = b - __bfloat162float(hb);
    asm("cvt.rn.bf16x2.f32 %0, %1, %2;" : "=r"(lo) : "f"(rb), "f"(ra));
}

__device__ __forceinline__ void ldm4(uint32_t* r, uint32_t addr) {
    asm volatile("ldmatrix.sync.aligned.m8n8.x4.shared.b16 {%0,%1,%2,%3}, [%4];"
        : "=r"(r[0]), "=r"(r[1]), "=r"(r[2]), "=r"(r[3]) : "r"(addr));
}

__device__ __forceinline__ void mma16816(float* c, const uint32_t* a, uint32_t b0, uint32_t b1) {
    asm volatile("mma.sync.aligned.m16n8k16.row.col.f32.bf16.bf16.f32 "
        "{%0,%1,%2,%3}, {%4,%5,%6,%7}, {%8,%9}, {%0,%1,%2,%3};"
        : "+f"(c[0]), "+f"(c[1]), "+f"(c[2]), "+f"(c[3])
        : "r"(a[0]), "r"(a[1]), "r"(a[2]), "r"(a[3]), "r"(b0), "r"(b1));
}

__device__ __forceinline__ void redv4(float* p, float a, float b, float c, float d) {
    asm volatile("red.global.add.v4.f32 [%0], {%1,%2,%3,%4};"
        :: "l"(p), "f"(a), "f"(b), "f"(c), "f"(d) : "memory");
}

__device__ __forceinline__ void atomicMaxFloat(float* addr, float v) {
    if (v >= 0.0f) atomicMax((int*)addr, __float_as_int(v));
    else           atomicMin((unsigned int*)addr, __float_as_uint(v));
}

// cooperative: fp32 weight [NR x DK] row-major -> smem bf16 hi/lo, row pitch RS bytes
__device__ __forceinline__ void load_w_smem(char* sm, int off_h, int off_l,
                                            const float* __restrict__ w,
                                            int NR, int DK, int RS, int tid) {
    int half = DK >> 1;
    for (int e = tid; e < NR * half; e += 256) {
        int r = e / half, k2 = e - r * half;
        float2 v = *(const float2*)(w + r * DK + k2 * 2);
        uint32_t h, l;
        split_pair(v.x, v.y, h, l);
        int byte = r * RS + k2 * 4;
        *(uint32_t*)(sm + off_h + byte) = h;
        *(uint32_t*)(sm + off_l + byte) = l;
    }
}

// warp tile: 16(M) x NT8*8(N), K = DK, 3-term bf16 split
template <int DK, int NT8>
__device__ __forceinline__ void warp_gemm(uint32_t xh, uint32_t xl,
                                          uint32_t wh, uint32_t wl,
                                          int RSX, int RSW,
                                          int wm, int wn, int lane, float* c) {
#pragma unroll
    for (int i = 0; i < NT8 * 4; i++) c[i] = 0.f;
    uint32_t aoff = (uint32_t)(wm * 16 + (lane & 15)) * RSX + (lane >> 4) * 16;
#pragma unroll
    for (int kc = 0; kc < DK / 16; kc++) {
        uint32_t ah[4], al[4];
        ldm4(ah, xh + aoff + kc * 32);
        ldm4(al, xl + aoff + kc * 32);
#pragma unroll
        for (int ntp = 0; ntp < NT8 / 2; ntp++) {
            uint32_t n = (uint32_t)(wn * (NT8 * 8) + ntp * 16 + (lane & 15));
            uint32_t boff = n * RSW + kc * 32 + (lane >> 4) * 16;
            uint32_t bh[4], bl[4];
            ldm4(bh, wh + boff);
            ldm4(bl, wl + boff);
            float* c0 = c + (2 * ntp) * 4;
            float* c1 = c + (2 * ntp + 1) * 4;
            mma16816(c0, ah, bh[0], bh[2]);
            mma16816(c0, ah, bl[0], bl[2]);
            mma16816(c0, al, bh[0], bh[2]);
            mma16816(c1, ah, bh[1], bh[3]);
            mma16816(c1, ah, bl[1], bl[3]);
            mma16816(c1, al, bh[1], bh[3]);
        }
    }
}

// ------------------------------- K0: init -----------------------------------
__global__ void k_init() {
    long long i = (long long)blockIdx.x * blockDim.x + threadIdx.x;
    if (i == 0) g_maxoff = -3.402823466e38f;
    long long n4 = (long long)NNODES * 64 / 4;
    if (i < n4) ((float4*)g_expsum)[i] = make_float4(0.f, 0.f, 0.f, 0.f);
}

// --------------- K1..K3: relation MLP + fused exp scatter -------------------
// 256 threads = 8 warps (4 M x 2 N), 64 tuples/CTA.
template <int AR>
__global__ void __launch_bounds__(256)
k_rel_mma(const float* __restrict__ ns, const int* __restrict__ idx,
          const float* __restrict__ w1, const float* __restrict__ b1,
          const float* __restrict__ w2, const float* __restrict__ b2, int T) {
    constexpr int D = AR * 64;
    constexpr int ND2 = D / 2;
    constexpr int NT8 = ND2 / 8;
    constexpr int RS = (D + 8) * 2;         // bytes per smem row (bf16, padded)
    constexpr int XSZ = 64 * RS;
    constexpr int WOFF = 2 * XSZ;
    constexpr int WSZ = D * RS;
    constexpr int BOFF = WOFF + 2 * WSZ;

    extern __shared__ char sm[];
    uint32_t sb = smem_u32(sm);
    uint32_t xh = sb, xl = sb + XSZ, wh = sb + WOFF, wl = sb + WOFF + WSZ;
    float* b1s = (float*)(sm + BOFF);
    float* b2s = b1s + D;
    float* wmax = b2s + D;
    float* obuf = (float*)(sm + WOFF);      // 64 x (D+1) fp32, reuses W region

    const int tid = threadIdx.x;
    const int wid = tid >> 5, lane = tid & 31;
    const int wm = wid >> 1, wn = wid & 1;
    const int t0 = blockIdx.x * 64;

    // gather X (bf16 hi/lo) into xs
    for (int e = tid; e < 64 * AR * 16; e += 256) {
        int slot = e >> 4, fq = e & 15;
        int t = slot / AR, p = slot - t * AR;
        float4 v = make_float4(0.f, 0.f, 0.f, 0.f);
        if (t0 + t < T) {
            int node = idx[(t0 + t) * AR + p];
            v = *(const float4*)(ns + (long long)node * 64 + fq * 4);
        }
        uint32_t h0, l0, h1, l1;
        split_pair(v.x, v.y, h0, l0);
        split_pair(v.z, v.w, h1, l1);
        int byte = t * RS + (p * 64 + fq * 4) * 2;
        *(uint32_t*)(sm + byte) = h0;
        *(uint32_t*)(sm + byte + 4) = h1;
        *(uint32_t*)(sm + XSZ + byte) = l0;
        *(uint32_t*)(sm + XSZ + byte + 4) = l1;
    }
    load_w_smem(sm, WOFF, WOFF + WSZ, w1, D, D, RS, tid);
    if (tid < D) { b1s[tid] = b1[tid]; b2s[tid] = b2[tid]; }
    __syncthreads();

    float c[NT8 * 4];
    // layer 1
    warp_gemm<D, NT8>(xh, xl, wh, wl, RS, RS, wm, wn, lane, c);
    __syncthreads();

    // epilogue 1: bias + relu -> xs (hi/lo)
#pragma unroll
    for (int nt = 0; nt < NT8; nt++) {
        int col = wn * ND2 + nt * 8 + (lane & 3) * 2;
        float bb0 = b1s[col], bb1 = b1s[col + 1];
        int r0 = wm * 16 + (lane >> 2);
        float v0 = fmaxf(c[nt * 4 + 0] + bb0, 0.f), v1 = fmaxf(c[nt * 4 + 1] + bb1, 0.f);
        float v2 = fmaxf(c[nt * 4 + 2] + bb0, 0.f), v3 = fmaxf(c[nt * 4 + 3] + bb1, 0.f);
        uint32_t h, l;
        int byte0 = r0 * RS + col * 2;
        split_pair(v0, v1, h, l);
        *(uint32_t*)(sm + byte0) = h;
        *(uint32_t*)(sm + XSZ + byte0) = l;
        int byte1 = (r0 + 8) * RS + col * 2;
        split_pair(v2, v3, h, l);
        *(uint32_t*)(sm + byte1) = h;
        *(uint32_t*)(sm + XSZ + byte1) = l;
    }
    load_w_smem(sm, WOFF, WOFF + WSZ, w2, D, D, RS, tid);
    __syncthreads();

    // layer 2
    warp_gemm<D, NT8>(xh, xl, wh, wl, RS, RS, wm, wn, lane, c);
    __syncthreads();   // all warps done reading W region before obuf overwrite

    // epilogue 2: stage o + per-CTA max
    float m = -3.402823466e38f;
    {
        int r0 = wm * 16 + (lane >> 2);
        bool ok0 = (t0 + r0) < T;
        bool ok1 = (t0 + r0 + 8) < T;
#pragma unroll
        for (int nt = 0; nt < NT8; nt++) {
            int col = wn * ND2 + nt * 8 + (lane & 3) * 2;
            float bb0 = b2s[col], bb1 = b2s[col + 1];
            float v0 = c[nt * 4 + 0] + bb0, v1 = c[nt * 4 + 1] + bb1;
            float v2 = c[nt * 4 + 2] + bb0, v3 = c[nt * 4 + 3] + bb1;
            obuf[r0 * (D + 1) + col] = v0;
            obuf[r0 * (D + 1) + col + 1] = v1;
            obuf[(r0 + 8) * (D + 1) + col] = v2;
            obuf[(r0 + 8) * (D + 1) + col + 1] = v3;
            if (ok0) m = fmaxf(m, fmaxf(v0, v1));
            if (ok1) m = fmaxf(m, fmaxf(v2, v3));
        }
    }
#pragma unroll
    for (int s = 16; s > 0; s >>= 1) m = fmaxf(m, __shfl_xor_sync(0xffffffffu, m, s));
    if (lane == 0) wmax[wid] = m;
    __syncthreads();
    if (tid == 0) {
        float bm = wmax[0];
#pragma unroll
        for (int w = 1; w < 8; w++) bm = fmaxf(bm, wmax[w]);
        atomicMaxFloat(&g_maxoff, bm);
    }

    // fused exp + v4 scatter-reduce
    for (int e = tid; e < 64 * (D / 4); e += 256) {
        int t = e / (D / 4), q = e - t * (D / 4);
        if (t0 + t >= T) continue;
        int col = q * 4, p = col >> 6, f = col & 63;
        int node = idx[(t0 + t) * AR + p];
        const float* orow = obuf + t * (D + 1) + col;
        float a = __expf(8.f * orow[0]);
        float b = __expf(8.f * orow[1]);
        float cc = __expf(8.f * orow[2]);
        float d = __expf(8.f * orow[3]);
        redv4(&g_expsum[(long long)node * 64 + f], a, b, cc, d);
    }
}

// --------------------------- K4: update MLP ---------------------------------
// cat = [1/8*log(eps'+S) | ns], D=128 -> 128 relu -> 64.
__global__ void __launch_bounds__(256)
k_update_mma(const float* __restrict__ ns,
             const float* __restrict__ w1, const float* __restrict__ b1,
             const float* __restrict__ w2, const float* __restrict__ b2,
             float* __restrict__ out) {
    constexpr int D = 128;
    constexpr int RS = (D + 8) * 2;         // 272
    constexpr int XSZ = 64 * RS;            // 17408
    constexpr int WOFF = 2 * XSZ;           // 34816
    constexpr int WSZ = D * RS;             // 34816
    constexpr int BOFF = WOFF + 2 * WSZ;    // 104448

    extern __shared__ char sm[];
    uint32_t sb = smem_u32(sm);
    uint32_t xh = sb, xl = sb + XSZ, wh = sb + WOFF, wl = sb + WOFF + WSZ;
    float* b1s = (float*)(sm + BOFF);
    float* b2s = b1s + 128;
    float* obuf = (float*)(sm + WOFF);      // 64 x 65 fp32

    const int tid = threadIdx.x;
    const int wid = tid >> 5, lane = tid & 31;
    const int wm = wid >> 1, wn = wid & 1;
    const int n0 = blockIdx.x * 64;
    const float eps2 = 1e-16f * __expf(8.f * g_maxoff);

    // gather cat rows -> xs
    for (int e = tid; e < 64 * 32; e += 256) {
        int t = e >> 5, q = e & 31;
        int col = q * 4;
        long long n = n0 + t;
        float4 v;
        if (col < 64) {
            float4 s = *(const float4*)(g_expsum + n * 64 + col);
            v = make_float4(0.125f * __logf(eps2 + s.x), 0.125f * __logf(eps2 + s.y),
                            0.125f * __logf(eps2 + s.z), 0.125f * __logf(eps2 + s.w));
        } else {
            v = *(const float4*)(ns + n * 64 + (col - 64));
        }
        uint32_t h0, l0, h1, l1;
        split_pair(v.x, v.y, h0, l0);
        split_pair(v.z, v.w, h1, l1);
        int byte = t * RS + col * 2;
        *(uint32_t*)(sm + byte) = h0;
        *(uint32_t*)(sm + byte + 4) = h1;
        *(uint32_t*)(sm + XSZ + byte) = l0;
        *(uint32_t*)(sm + XSZ + byte + 4) = l1;
    }
    load_w_smem(sm, WOFF, WOFF + WSZ, w1, 128, 128, RS, tid);
    if (tid < 128) b1s[tid] = b1[tid];
    if (tid < 64) b2s[tid] = b2[tid];
    __syncthreads();

    float c[32];
    // layer 1: N=128, warp half = 64 -> NT8=8
    warp_gemm<128, 8>(xh, xl, wh, wl, RS, RS, wm, wn, lane, c);
    __syncthreads();

#pragma unroll
    for (int nt = 0; nt < 8; nt++) {
        int col = wn * 64 + nt * 8 + (lane & 3) * 2;
        float bb0 = b1s[col], bb1 = b1s[col + 1];
        int r0 = wm * 16 + (lane >> 2);
        float v0 = fmaxf(c[nt * 4 + 0] + bb0, 0.f), v1 = fmaxf(c[nt * 4 + 1] + bb1, 0.f);
        float v2 = fmaxf(c[nt * 4 + 2] + bb0, 0.f), v3 = fmaxf(c[nt * 4 + 3] + bb1, 0.f);
        uint32_t h, l;
        int byte0 = r0 * RS + col * 2;
        split_pair(v0, v1, h, l);
        *(uint32_t*)(sm + byte0) = h;
        *(uint32_t*)(sm + XSZ + byte0) = l;
        int byte1 = (r0 + 8) * RS + col * 2;
        split_pair(v2, v3, h, l);
        *(uint32_t*)(sm + byte1) = h;
        *(uint32_t*)(sm + XSZ + byte1) = l;
    }
    load_w_smem(sm, WOFF, WOFF + WSZ, w2, 64, 128, RS, tid);
    __syncthreads();

    // layer 2: N=64, warp half = 32 -> NT8=4
    warp_gemm<128, 4>(xh, xl, wh, wl, RS, RS, wm, wn, lane, c);
    __syncthreads();

#pragma unroll
    for (int nt = 0; nt < 4; nt++) {
        int col = wn * 32 + nt * 8 + (lane & 3) * 2;
        float bb0 = b2s[col], bb1 = b2s[col + 1];
        int r0 = wm * 16 + (lane >> 2);
        obuf[r0 * 65 + col] = c[nt * 4 + 0] + bb0;
        obuf[r0 * 65 + col + 1] = c[nt * 4 + 1] + bb1;
        obuf[(r0 + 8) * 65 + col] = c[nt * 4 + 2] + bb0;
        obuf[(r0 + 8) * 65 + col + 1] = c[nt * 4 + 3] + bb1;
    }
    __syncthreads();
    for (int e = tid; e < 64 * 64; e += 256) {
        int t = e >> 6, col = e & 63;
        out[(long long)(n0 + t) * 64 + col] = obuf[t * 65 + col];
    }
}

// ---------------------------------------------------------------------------
extern "C" void kernel_launch(void* const* d_in, const int* in_sizes, int n_in,
                              void* d_out, int out_size) {
    const float* ns   = (const float*)d_in[0];
    const int*   idx0 = (const int*)d_in[1];
    const int*   idx1 = (const int*)d_in[2];
    const int*   idx2 = (const int*)d_in[3];
    const float* r0w1 = (const float*)d_in[4];
    const float* r0b1 = (const float*)d_in[5];
    const float* r0w2 = (const float*)d_in[6];
    const float* r0b2 = (const float*)d_in[7];
    const float* r1w1 = (const float*)d_in[8];
    const float* r1b1 = (const float*)d_in[9];
    const float* r1w2 = (const float*)d_in[10];
    const float* r1b2 = (const float*)d_in[11];
    const float* r2w1 = (const float*)d_in[12];
    const float* r2b1 = (const float*)d_in[13];
    const float* r2w2 = (const float*)d_in[14];
    const float* r2b2 = (const float*)d_in[15];
    const float* uw1  = (const float*)d_in[16];
    const float* ub1  = (const float*)d_in[17];
    const float* uw2  = (const float*)d_in[18];
    const float* ub2  = (const float*)d_in[19];
    float* out = (float*)d_out;

    const int T01 = 300000, T2 = 200000;

    const int SMA2 = 2 * (64 * 272) + 2 * (128 * 272) + 2 * 128 * 4 + 64;  // ~105.6KB
    const int SMA3 = 2 * (64 * 400) + 2 * (192 * 400) + 2 * 192 * 4 + 64;  // ~206.4KB
    const int SMU  = 2 * (64 * 272) + 2 * (128 * 272) + 128 * 4 + 64 * 4 + 64;
    cudaFuncSetAttribute(k_rel_mma<2>, cudaFuncAttributeMaxDynamicSharedMemorySize, SMA2);
    cudaFuncSetAttribute(k_rel_mma<3>, cudaFuncAttributeMaxDynamicSharedMemorySize, SMA3);
    cudaFuncSetAttribute(k_update_mma, cudaFuncAttributeMaxDynamicSharedMemorySize, SMU);

    // K0
    {
        long long n4 = (long long)NNODES * 64 / 4;
        k_init<<<(int)((n4 + 255) / 256), 256>>>();
    }

    // K1..K3 (fused MLP + scatter)
    k_rel_mma<2><<<(T01 + 63) / 64, 256, SMA2>>>(ns, idx0, r0w1, r0b1, r0w2, r0b2, T01);
    k_rel_mma<2><<<(T01 + 63) / 64, 256, SMA2>>>(ns, idx1, r1w1, r1b1, r1w2, r1b2, T01);
    k_rel_mma<3><<<(T2 + 63) / 64, 256, SMA3>>>(ns, idx2, r2w1, r2b1, r2w2, r2b2, T2);

    // K4
    k_update_mma<<<(NNODES + 63) / 64, 256, SMU>>>(ns, uw1, ub1, uw2, ub2, out);
}

// round 9
// speedup vs baseline: 5.0537x; 1.5051x over previous
#include <cuda_runtime.h>
#include <cuda_fp16.h>
#include <cstdint>

// ---------------------------------------------------------------------------
// RelationMessagePassing (sm_103) — round 8: fp16 2-term split mma.sync
//   o ~= (Ah + Al) @ Wh   with A,W fp16; error ~2^-11 (weight rounding)
// Weights pre-converted to fp16 once (pre-kernel). Fused exp-scatter epilogue:
//   msg = (1/8)*log(1e-16*e^{8*max} + sum exp(8*o))
// ---------------------------------------------------------------------------

#define NNODES 200000

__device__ float g_expsum[NNODES * 64];
__device__ float g_maxoff;
__device__ __half g_wh[163840];   // all weight matrices as fp16

// ------------------------------ helpers ------------------------------------
__device__ __forceinline__ uint32_t smem_u32(const void* p) {
    uint32_t a;
    asm("{ .reg .u64 t; cvta.to.shared.u64 t, %1; cvt.u32.u64 %0, t; }"
        : "=r"(a) : "l"(p));
    return a;
}

// split fp32 pair -> fp16x2 hi word + fp16x2 residual word (elem0 in low half)
__device__ __forceinline__ void split_pair_h(float a, float b, uint32_t& hi, uint32_t& lo) {
    __half2 hp = __floats2half2_rn(a, b);
    hi = *reinterpret_cast<uint32_t*>(&hp);
    float ra = a - __half2float(__low2half(hp));
    float rb = b - __half2float(__high2half(hp));
    __half2 lp = __floats2half2_rn(ra, rb);
    lo = *reinterpret_cast<uint32_t*>(&lp);
}

__device__ __forceinline__ void ldm4(uint32_t* r, uint32_t addr) {
    asm volatile("ldmatrix.sync.aligned.m8n8.x4.shared.b16 {%0,%1,%2,%3}, [%4];"
        : "=r"(r[0]), "=r"(r[1]), "=r"(r[2]), "=r"(r[3]) : "r"(addr));
}

__device__ __forceinline__ void mma16816(float* c, const uint32_t* a, uint32_t b0, uint32_t b1) {
    asm volatile("mma.sync.aligned.m16n8k16.row.col.f32.f16.f16.f32 "
        "{%0,%1,%2,%3}, {%4,%5,%6,%7}, {%8,%9}, {%0,%1,%2,%3};"
        : "+f"(c[0]), "+f"(c[1]), "+f"(c[2]), "+f"(c[3])
        : "r"(a[0]), "r"(a[1]), "r"(a[2]), "r"(a[3]), "r"(b0), "r"(b1));
}

__device__ __forceinline__ void redv4(float* p, float a, float b, float c, float d) {
    asm volatile("red.global.add.v4.f32 [%0], {%1,%2,%3,%4};"
        :: "l"(p), "f"(a), "f"(b), "f"(c), "f"(d) : "memory");
}

__device__ __forceinline__ void atomicMaxFloat(float* addr, float v) {
    if (v >= 0.0f) atomicMax((int*)addr, __float_as_int(v));
    else           atomicMin((unsigned int*)addr, __float_as_uint(v));
}

// copy fp16 weight [NR x DK] row-major from g_wh into smem rows of pitch RS bytes
__device__ __forceinline__ void copy_w_smem(char* sm, int off, long long wo,
                                            int NR, int DK, int RS, int tid) {
    const uint4* src = (const uint4*)(g_wh + wo);
    int n8 = DK >> 3;
    for (int e = tid; e < NR * n8; e += 256) {
        int r = e / n8, k8 = e - r * n8;
        *(uint4*)(sm + off + r * RS + k8 * 16) = src[e];
    }
}

// warp tile: 16(M) x NT8*8(N), K = DK; 2-term: (Ah + Al) @ Bh
template <int DK, int NT8>
__device__ __forceinline__ void warp_gemm(uint32_t xh, uint32_t xl, uint32_t wh,
                                          int RSX, int RSW,
                                          int wm, int wn, int lane, float* c) {
#pragma unroll
    for (int i = 0; i < NT8 * 4; i++) c[i] = 0.f;
    uint32_t aoff = (uint32_t)(wm * 16 + (lane & 15)) * RSX + (lane >> 4) * 16;
#pragma unroll
    for (int kc = 0; kc < DK / 16; kc++) {
        uint32_t ah[4], al[4];
        ldm4(ah, xh + aoff + kc * 32);
        ldm4(al, xl + aoff + kc * 32);
#pragma unroll
        for (int ntp = 0; ntp < NT8 / 2; ntp++) {
            uint32_t n = (uint32_t)(wn * (NT8 * 8) + ntp * 16 + (lane & 15));
            uint32_t boff = n * RSW + kc * 32 + (lane >> 4) * 16;
            uint32_t bh[4];
            ldm4(bh, wh + boff);
            float* c0 = c + (2 * ntp) * 4;
            float* c1 = c + (2 * ntp + 1) * 4;
            mma16816(c0, ah, bh[0], bh[2]);
            mma16816(c0, al, bh[0], bh[2]);
            mma16816(c1, ah, bh[1], bh[3]);
            mma16816(c1, al, bh[1], bh[3]);
        }
    }
}

// ---------------------- K-1: weights fp32 -> fp16 ---------------------------
__global__ void k_w2h(const float* __restrict__ src, long long dstoff, int n) {
    int i = blockIdx.x * blockDim.x + threadIdx.x;
    if (i < n) g_wh[dstoff + i] = __float2half(src[i]);
}

// ------------------------------- K0: init -----------------------------------
__global__ void k_init() {
    long long i = (long long)blockIdx.x * blockDim.x + threadIdx.x;
    if (i == 0) g_maxoff = -3.402823466e38f;
    long long n4 = (long long)NNODES * 64 / 4;
    if (i < n4) ((float4*)g_expsum)[i] = make_float4(0.f, 0.f, 0.f, 0.f);
}

// --------------- K1..K3: relation MLP + fused exp scatter -------------------
// 256 threads = 8 warps (4 M x 2 N), 64 tuples/CTA.
template <int AR>
__global__ void __launch_bounds__(256)
k_rel_mma(const float* __restrict__ ns, const int* __restrict__ idx,
          long long w1o, const float* __restrict__ b1,
          long long w2o, const float* __restrict__ b2, int T) {
    constexpr int D = AR * 64;
    constexpr int ND2 = D / 2;
    constexpr int NT8 = ND2 / 8;
    constexpr int RS = (D + 8) * 2;         // bytes per smem row (fp16, padded)
    constexpr int XSZ = 64 * RS;
    constexpr int WOFF = 2 * XSZ;
    constexpr int WSZ = D * RS;
    constexpr int BOFF = WOFF + WSZ;

    extern __shared__ char sm[];
    uint32_t sb = smem_u32(sm);
    uint32_t xh = sb, xl = sb + XSZ, wh = sb + WOFF;
    float* b1s = (float*)(sm + BOFF);
    float* b2s = b1s + D;
    float* wmax = b2s + D;
    float* obuf = (float*)(sm + WOFF);      // 64 x (D+1) fp32, reuses W region

    const int tid = threadIdx.x;
    const int wid = tid >> 5, lane = tid & 31;
    const int wm = wid >> 1, wn = wid & 1;
    const int t0 = blockIdx.x * 64;

    // gather X (fp16 hi/lo) into xs
    for (int e = tid; e < 64 * AR * 16; e += 256) {
        int slot = e >> 4, fq = e & 15;
        int t = slot / AR, p = slot - t * AR;
        float4 v = make_float4(0.f, 0.f, 0.f, 0.f);
        if (t0 + t < T) {
            int node = idx[(t0 + t) * AR + p];
            v = *(const float4*)(ns + (long long)node * 64 + fq * 4);
        }
        uint32_t h0, l0, h1, l1;
        split_pair_h(v.x, v.y, h0, l0);
        split_pair_h(v.z, v.w, h1, l1);
        int byte = t * RS + (p * 64 + fq * 4) * 2;
        *(uint32_t*)(sm + byte) = h0;
        *(uint32_t*)(sm + byte + 4) = h1;
        *(uint32_t*)(sm + XSZ + byte) = l0;
        *(uint32_t*)(sm + XSZ + byte + 4) = l1;
    }
    copy_w_smem(sm, WOFF, w1o, D, D, RS, tid);
    if (tid < D) { b1s[tid] = b1[tid]; b2s[tid] = b2[tid]; }
    __syncthreads();

    float c[NT8 * 4];
    // layer 1
    warp_gemm<D, NT8>(xh, xl, wh, RS, RS, wm, wn, lane, c);
    __syncthreads();

    // epilogue 1: bias + relu -> xs (hi/lo)
#pragma unroll
    for (int nt = 0; nt < NT8; nt++) {
        int col = wn * ND2 + nt * 8 + (lane & 3) * 2;
        float bb0 = b1s[col], bb1 = b1s[col + 1];
        int r0 = wm * 16 + (lane >> 2);
        float v0 = fmaxf(c[nt * 4 + 0] + bb0, 0.f), v1 = fmaxf(c[nt * 4 + 1] + bb1, 0.f);
        float v2 = fmaxf(c[nt * 4 + 2] + bb0, 0.f), v3 = fmaxf(c[nt * 4 + 3] + bb1, 0.f);
        uint32_t h, l;
        int byte0 = r0 * RS + col * 2;
        split_pair_h(v0, v1, h, l);
        *(uint32_t*)(sm + byte0) = h;
        *(uint32_t*)(sm + XSZ + byte0) = l;
        int byte1 = (r0 + 8) * RS + col * 2;
        split_pair_h(v2, v3, h, l);
        *(uint32_t*)(sm + byte1) = h;
        *(uint32_t*)(sm + XSZ + byte1) = l;
    }
    copy_w_smem(sm, WOFF, w2o, D, D, RS, tid);
    __syncthreads();

    // layer 2
    warp_gemm<D, NT8>(xh, xl, wh, RS, RS, wm, wn, lane, c);
    __syncthreads();   // all warps done reading W region before obuf overwrite

    // epilogue 2: stage o + per-CTA max
    float m = -3.402823466e38f;
    {
        int r0 = wm * 16 + (lane >> 2);
        bool ok0 = (t0 + r0) < T;
        bool ok1 = (t0 + r0 + 8) < T;
#pragma unroll
        for (int nt = 0; nt < NT8; nt++) {
            int col = wn * ND2 + nt * 8 + (lane & 3) * 2;
            float bb0 = b2s[col], bb1 = b2s[col + 1];
            float v0 = c[nt * 4 + 0] + bb0, v1 = c[nt * 4 + 1] + bb1;
            float v2 = c[nt * 4 + 2] + bb0, v3 = c[nt * 4 + 3] + bb1;
            obuf[r0 * (D + 1) + col] = v0;
            obuf[r0 * (D + 1) + col + 1] = v1;
            obuf[(r0 + 8) * (D + 1) + col] = v2;
            obuf[(r0 + 8) * (D + 1) + col + 1] = v3;
            if (ok0) m = fmaxf(m, fmaxf(v0, v1));
            if (ok1) m = fmaxf(m, fmaxf(v2, v3));
        }
    }
#pragma unroll
    for (int s = 16; s > 0; s >>= 1) m = fmaxf(m, __shfl_xor_sync(0xffffffffu, m, s));
    if (lane == 0) wmax[wid] = m;
    __syncthreads();
    if (tid == 0) {
        float bm = wmax[0];
#pragma unroll
        for (int w = 1; w < 8; w++) bm = fmaxf(bm, wmax[w]);
        atomicMaxFloat(&g_maxoff, bm);
    }

    // fused exp + v4 scatter-reduce
    for (int e = tid; e < 64 * (D / 4); e += 256) {
        int t = e / (D / 4), q = e - t * (D / 4);
        if (t0 + t >= T) continue;
        int col = q * 4, p = col >> 6, f = col & 63;
        int node = idx[(t0 + t) * AR + p];
        const float* orow = obuf + t * (D + 1) + col;
        float a = __expf(8.f * orow[0]);
        float b = __expf(8.f * orow[1]);
        float cc = __expf(8.f * orow[2]);
        float d = __expf(8.f * orow[3]);
        redv4(&g_expsum[(long long)node * 64 + f], a, b, cc, d);
    }
}

// --------------------------- K4: update MLP ---------------------------------
__global__ void __launch_bounds__(256)
k_update_mma(const float* __restrict__ ns,
             long long w1o, const float* __restrict__ b1,
             long long w2o, const float* __restrict__ b2,
             float* __restrict__ out) {
    constexpr int D = 128;
    constexpr int RS = (D + 8) * 2;         // 272
    constexpr int XSZ = 64 * RS;            // 17408
    constexpr int WOFF = 2 * XSZ;           // 34816
    constexpr int WSZ = D * RS;             // 34816
    constexpr int BOFF = WOFF + WSZ;        // 69632

    extern __shared__ char sm[];
    uint32_t sb = smem_u32(sm);
    uint32_t xh = sb, xl = sb + XSZ, wh = sb + WOFF;
    float* b1s = (float*)(sm + BOFF);
    float* b2s = b1s + 128;
    float* obuf = (float*)(sm + WOFF);      // 64 x 65 fp32

    const int tid = threadIdx.x;
    const int wid = tid >> 5, lane = tid & 31;
    const int wm = wid >> 1, wn = wid & 1;
    const int n0 = blockIdx.x * 64;
    const float eps2 = 1e-16f * __expf(8.f * g_maxoff);

    // gather cat = [1/8*log(eps'+S) | ns] rows -> xs
    for (int e = tid; e < 64 * 32; e += 256) {
        int t = e >> 5, q = e & 31;
        int col = q * 4;
        long long n = n0 + t;
        float4 v;
        if (col < 64) {
            float4 s = *(const float4*)(g_expsum + n * 64 + col);
            v = make_float4(0.125f * __logf(eps2 + s.x), 0.125f * __logf(eps2 + s.y),
                            0.125f * __logf(eps2 + s.z), 0.125f * __logf(eps2 + s.w));
        } else {
            v = *(const float4*)(ns + n * 64 + (col - 64));
        }
        uint32_t h0, l0, h1, l1;
        split_pair_h(v.x, v.y, h0, l0);
        split_pair_h(v.z, v.w, h1, l1);
        int byte = t * RS + col * 2;
        *(uint32_t*)(sm + byte) = h0;
        *(uint32_t*)(sm + byte + 4) = h1;
        *(uint32_t*)(sm + XSZ + byte) = l0;
        *(uint32_t*)(sm + XSZ + byte + 4) = l1;
    }
    copy_w_smem(sm, WOFF, w1o, 128, 128, RS, tid);
    if (tid < 128) b1s[tid] = b1[tid];
    if (tid < 64) b2s[tid] = b2[tid];
    __syncthreads();

    float c[32];
    // layer 1: N=128, warp half = 64 -> NT8=8
    warp_gemm<128, 8>(xh, xl, wh, RS, RS, wm, wn, lane, c);
    __syncthreads();

#pragma unroll
    for (int nt = 0; nt < 8; nt++) {
        int col = wn * 64 + nt * 8 + (lane & 3) * 2;
        float bb0 = b1s[col], bb1 = b1s[col + 1];
        int r0 = wm * 16 + (lane >> 2);
        float v0 = fmaxf(c[nt * 4 + 0] + bb0, 0.f), v1 = fmaxf(c[nt * 4 + 1] + bb1, 0.f);
        float v2 = fmaxf(c[nt * 4 + 2] + bb0, 0.f), v3 = fmaxf(c[nt * 4 + 3] + bb1, 0.f);
        uint32_t h, l;
        int byte0 = r0 * RS + col * 2;
        split_pair_h(v0, v1, h, l);
        *(uint32_t*)(sm + byte0) = h;
        *(uint32_t*)(sm + XSZ + byte0) = l;
        int byte1 = (r0 + 8) * RS + col * 2;
        split_pair_h(v2, v3, h, l);
        *(uint32_t*)(sm + byte1) = h;
        *(uint32_t*)(sm + XSZ + byte1) = l;
    }
    copy_w_smem(sm, WOFF, w2o, 64, 128, RS, tid);
    __syncthreads();

    // layer 2: N=64, warp half = 32 -> NT8=4
    warp_gemm<128, 4>(xh, xl, wh, RS, RS, wm, wn, lane, c);
    __syncthreads();

#pragma unroll
    for (int nt = 0; nt < 4; nt++) {
        int col = wn * 32 + nt * 8 + (lane & 3) * 2;
        float bb0 = b2s[col], bb1 = b2s[col + 1];
        int r0 = wm * 16 + (lane >> 2);
        obuf[r0 * 65 + col] = c[nt * 4 + 0] + bb0;
        obuf[r0 * 65 + col + 1] = c[nt * 4 + 1] + bb1;
        obuf[(r0 + 8) * 65 + col] = c[nt * 4 + 2] + bb0;
        obuf[(r0 + 8) * 65 + col + 1] = c[nt * 4 + 3] + bb1;
    }
    __syncthreads();
    for (int e = tid; e < 64 * 64; e += 256) {
        int t = e >> 6, col = e & 63;
        out[(long long)(n0 + t) * 64 + col] = obuf[t * 65 + col];
    }
}

// ---------------------------------------------------------------------------
extern "C" void kernel_launch(void* const* d_in, const int* in_sizes, int n_in,
                              void* d_out, int out_size) {
    const float* ns   = (const float*)d_in[0];
    const int*   idx0 = (const int*)d_in[1];
    const int*   idx1 = (const int*)d_in[2];
    const int*   idx2 = (const int*)d_in[3];
    const float* r0w1 = (const float*)d_in[4];
    const float* r0b1 = (const float*)d_in[5];
    const float* r0w2 = (const float*)d_in[6];
    const float* r0b2 = (const float*)d_in[7];
    const float* r1w1 = (const float*)d_in[8];
    const float* r1b1 = (const float*)d_in[9];
    const float* r1w2 = (const float*)d_in[10];
    const float* r1b2 = (const float*)d_in[11];
    const float* r2w1 = (const float*)d_in[12];
    const float* r2b1 = (const float*)d_in[13];
    const float* r2w2 = (const float*)d_in[14];
    const float* r2b2 = (const float*)d_in[15];
    const float* uw1  = (const float*)d_in[16];
    const float* ub1  = (const float*)d_in[17];
    const float* uw2  = (const float*)d_in[18];
    const float* ub2  = (const float*)d_in[19];
    float* out = (float*)d_out;

    const int T01 = 300000, T2 = 200000;

    // weight offsets in g_wh (elements)
    const long long O_R0W1 = 0, O_R0W2 = 16384, O_R1W1 = 32768, O_R1W2 = 49152;
    const long long O_R2W1 = 65536, O_R2W2 = 102400, O_UW1 = 139264, O_UW2 = 155648;

    const int SMA2 = 2 * (64 * 272) + 128 * 272 + 2 * 128 * 4 + 64;   // ~70.8KB
    const int SMA3 = 2 * (64 * 400) + 192 * 400 + 2 * 192 * 4 + 64;   // ~129.6KB
    const int SMU  = 2 * (64 * 272) + 128 * 272 + 128 * 4 + 64 * 4 + 64;
    cudaFuncSetAttribute(k_rel_mma<2>, cudaFuncAttributeMaxDynamicSharedMemorySize, SMA2);
    cudaFuncSetAttribute(k_rel_mma<3>, cudaFuncAttributeMaxDynamicSharedMemorySize, SMA3);
    cudaFuncSetAttribute(k_update_mma, cudaFuncAttributeMaxDynamicSharedMemorySize, SMU);

    // K-1: precompute fp16 weights
    k_w2h<<<(16384 + 255) / 256, 256>>>(r0w1, O_R0W1, 16384);
    k_w2h<<<(16384 + 255) / 256, 256>>>(r0w2, O_R0W2, 16384);
    k_w2h<<<(16384 + 255) / 256, 256>>>(r1w1, O_R1W1, 16384);
    k_w2h<<<(16384 + 255) / 256, 256>>>(r1w2, O_R1W2, 16384);
    k_w2h<<<(36864 + 255) / 256, 256>>>(r2w1, O_R2W1, 36864);
    k_w2h<<<(36864 + 255) / 256, 256>>>(r2w2, O_R2W2, 36864);
    k_w2h<<<(16384 + 255) / 256, 256>>>(uw1,  O_UW1,  16384);
    k_w2h<<<(8192  + 255) / 256, 256>>>(uw2,  O_UW2,  8192);

    // K0
    {
        long long n4 = (long long)NNODES * 64 / 4;
        k_init<<<(int)((n4 + 255) / 256), 256>>>();
    }

    // K1..K3 (fused MLP + scatter)
    k_rel_mma<2><<<(T01 + 63) / 64, 256, SMA2>>>(ns, idx0, O_R0W1, r0b1, O_R0W2, r0b2, T01);
    k_rel_mma<2><<<(T01 + 63) / 64, 256, SMA2>>>(ns, idx1, O_R1W1, r1b1, O_R1W2, r1b2, T01);
    k_rel_mma<3><<<(T2 + 63) / 64, 256, SMA3>>>(ns, idx2, O_R2W1, r2b1, O_R2W2, r2b2, T2);

    // K4
    k_update_mma<<<(NNODES + 63) / 64, 256, SMU>>>(ns, O_UW1, ub1, O_UW2, ub2, out);
}

// round 12
// speedup vs baseline: 5.7656x; 1.1409x over previous
#include <cuda_runtime.h>
#include <cuda_fp16.h>
#include <cstdint>

// ---------------------------------------------------------------------------
// RelationMessagePassing (sm_103) — round 9: fp16 2-term split mma.sync,
// warp M-tile = 32 (B-fragment reuse x2), register-direct fused exp-scatter
// epilogue (red.global.add.v2.f32, no smem staging).
//   msg = (1/8)*log(1e-16*e^{8*max} + sum exp(8*o))
// ---------------------------------------------------------------------------

#define NNODES 200000

__device__ float g_expsum[NNODES * 64];
__device__ float g_maxoff;
__device__ __half g_wh[163840];   // all weight matrices as fp16

// ------------------------------ helpers ------------------------------------
__device__ __forceinline__ uint32_t smem_u32(const void* p) {
    uint32_t a;
    asm("{ .reg .u64 t; cvta.to.shared.u64 t, %1; cvt.u32.u64 %0, t; }"
        : "=r"(a) : "l"(p));
    return a;
}

__device__ __forceinline__ void split_pair_h(float a, float b, uint32_t& hi, uint32_t& lo) {
    __half2 hp = __floats2half2_rn(a, b);
    hi = *reinterpret_cast<uint32_t*>(&hp);
    float ra = a - __half2float(__low2half(hp));
    float rb = b - __half2float(__high2half(hp));
    __half2 lp = __floats2half2_rn(ra, rb);
    lo = *reinterpret_cast<uint32_t*>(&lp);
}

__device__ __forceinline__ void ldm4(uint32_t* r, uint32_t addr) {
    asm volatile("ldmatrix.sync.aligned.m8n8.x4.shared.b16 {%0,%1,%2,%3}, [%4];"
        : "=r"(r[0]), "=r"(r[1]), "=r"(r[2]), "=r"(r[3]) : "r"(addr));
}

__device__ __forceinline__ void mma16816(float* c, const uint32_t* a, uint32_t b0, uint32_t b1) {
    asm volatile("mma.sync.aligned.m16n8k16.row.col.f32.f16.f16.f32 "
        "{%0,%1,%2,%3}, {%4,%5,%6,%7}, {%8,%9}, {%0,%1,%2,%3};"
        : "+f"(c[0]), "+f"(c[1]), "+f"(c[2]), "+f"(c[3])
        : "r"(a[0]), "r"(a[1]), "r"(a[2]), "r"(a[3]), "r"(b0), "r"(b1));
}

__device__ __forceinline__ void redv2(float* p, float a, float b) {
    asm volatile("red.global.add.v2.f32 [%0], {%1,%2};"
        :: "l"(p), "f"(a), "f"(b) : "memory");
}

__device__ __forceinline__ void atomicMaxFloat(float* addr, float v) {
    if (v >= 0.0f) atomicMax((int*)addr, __float_as_int(v));
    else           atomicMin((unsigned int*)addr, __float_as_uint(v));
}

// copy fp16 weight [NR x DK] row-major from g_wh into smem rows of pitch RS bytes
__device__ __forceinline__ void copy_w_smem(char* sm, int off, long long wo,
                                            int NR, int DK, int RS, int tid) {
    const uint4* src = (const uint4*)(g_wh + wo);
    int n8 = DK >> 3;
    for (int e = tid; e < NR * n8; e += 256) {
        int r = e / n8, k8 = e - r * n8;
        *(uint4*)(sm + off + r * RS + k8 * 16) = src[e];
    }
}

// warp tile: 32(M) x NT8*8(N), K = DK; 2-term: (Ah + Al) @ Bh
// c layout: c[0..NT8*4) = m-half 0, c[NT8*4..NT8*8) = m-half 1
template <int DK, int NT8>
__device__ __forceinline__ void warp_gemm32(uint32_t xh, uint32_t xl, uint32_t wh,
                                            int RSX, int RSW,
                                            int wm, int wn, int lane, float* c) {
#pragma unroll
    for (int i = 0; i < NT8 * 8; i++) c[i] = 0.f;
    uint32_t a0 = (uint32_t)(wm * 32 + (lane & 15)) * RSX + (lane >> 4) * 16;
    uint32_t a1 = a0 + 16 * RSX;
#pragma unroll
    for (int kc = 0; kc < DK / 16; kc++) {
        uint32_t ah0[4], al0[4], ah1[4], al1[4];
        ldm4(ah0, xh + a0 + kc * 32);
        ldm4(ah1, xh + a1 + kc * 32);
        ldm4(al0, xl + a0 + kc * 32);
        ldm4(al1, xl + a1 + kc * 32);
#pragma unroll
        for (int ntp = 0; ntp < NT8 / 2; ntp++) {
            uint32_t n = (uint32_t)(wn * (NT8 * 8) + ntp * 16 + (lane & 15));
            uint32_t boff = n * RSW + kc * 32 + (lane >> 4) * 16;
            uint32_t bh[4];
            ldm4(bh, wh + boff);
            float* c00 = c + (2 * ntp) * 4;
            float* c01 = c + (2 * ntp + 1) * 4;
            float* c10 = c00 + NT8 * 4;
            float* c11 = c01 + NT8 * 4;
            mma16816(c00, ah0, bh[0], bh[2]);
            mma16816(c00, al0, bh[0], bh[2]);
            mma16816(c01, ah0, bh[1], bh[3]);
            mma16816(c01, al0, bh[1], bh[3]);
            mma16816(c10, ah1, bh[0], bh[2]);
            mma16816(c10, al1, bh[0], bh[2]);
            mma16816(c11, ah1, bh[1], bh[3]);
            mma16816(c11, al1, bh[1], bh[3]);
        }
    }
}

// ---------------------- K-1: weights fp32 -> fp16 ---------------------------
__global__ void k_w2h(const float* __restrict__ src, long long dstoff, int n) {
    int i = blockIdx.x * blockDim.x + threadIdx.x;
    if (i < n) g_wh[dstoff + i] = __float2half(src[i]);
}

// ------------------------------- K0: init -----------------------------------
__global__ void k_init() {
    long long i = (long long)blockIdx.x * blockDim.x + threadIdx.x;
    if (i == 0) g_maxoff = -3.402823466e38f;
    long long n4 = (long long)NNODES * 64 / 4;
    if (i < n4) ((float4*)g_expsum)[i] = make_float4(0.f, 0.f, 0.f, 0.f);
}

// --------------- K1..K3: relation MLP + fused exp scatter -------------------
// 256 threads = 8 warps (4 M x 2 N), warp M=32 -> 128 tuples/CTA.
template <int AR, int MAXCTA>
__global__ void __launch_bounds__(256, MAXCTA)
k_rel_mma(const float* __restrict__ ns, const int* __restrict__ idx,
          long long w1o, const float* __restrict__ b1,
          long long w2o, const float* __restrict__ b2, int T) {
    constexpr int D = AR * 64;
    constexpr int ND2 = D / 2;
    constexpr int NT8 = ND2 / 8;
    constexpr int RS = (D + 8) * 2;         // bytes per smem row (fp16, padded)
    constexpr int XSZ = 128 * RS;
    constexpr int WOFF = 2 * XSZ;
    constexpr int WSZ = D * RS;
    constexpr int BOFF = WOFF + WSZ;

    extern __shared__ char sm[];
    uint32_t sb = smem_u32(sm);
    uint32_t xh = sb, xl = sb + XSZ, wh = sb + WOFF;
    float* b1s = (float*)(sm + BOFF);
    float* b2s = b1s + D;
    float* wmax = b2s + D;

    const int tid = threadIdx.x;
    const int wid = tid >> 5, lane = tid & 31;
    const int wm = wid >> 1, wn = wid & 1;
    const int t0 = blockIdx.x * 128;

    // gather X (fp16 hi/lo) into xs
    for (int e = tid; e < 128 * AR * 16; e += 256) {
        int slot = e >> 4, fq = e & 15;
        int t = slot / AR, p = slot - t * AR;
        float4 v = make_float4(0.f, 0.f, 0.f, 0.f);
        if (t0 + t < T) {
            int node = idx[(t0 + t) * AR + p];
            v = *(const float4*)(ns + (long long)node * 64 + fq * 4);
        }
        uint32_t h0, l0, h1, l1;
        split_pair_h(v.x, v.y, h0, l0);
        split_pair_h(v.z, v.w, h1, l1);
        int byte = t * RS + (p * 64 + fq * 4) * 2;
        *(uint32_t*)(sm + byte) = h0;
        *(uint32_t*)(sm + byte + 4) = h1;
        *(uint32_t*)(sm + XSZ + byte) = l0;
        *(uint32_t*)(sm + XSZ + byte + 4) = l1;
    }
    copy_w_smem(sm, WOFF, w1o, D, D, RS, tid);
    if (tid < D) { b1s[tid] = b1[tid]; b2s[tid] = b2[tid]; }
    __syncthreads();

    float c[NT8 * 8];
    // layer 1
    warp_gemm32<D, NT8>(xh, xl, wh, RS, RS, wm, wn, lane, c);
    __syncthreads();

    // epilogue 1: bias + relu -> xs (hi/lo)
#pragma unroll
    for (int h = 0; h < 2; h++) {
#pragma unroll
        for (int nt = 0; nt < NT8; nt++) {
            int col = wn * ND2 + nt * 8 + (lane & 3) * 2;
            float bb0 = b1s[col], bb1 = b1s[col + 1];
            int r0 = wm * 32 + h * 16 + (lane >> 2);
            const float* cc = c + h * NT8 * 4 + nt * 4;
            float v0 = fmaxf(cc[0] + bb0, 0.f), v1 = fmaxf(cc[1] + bb1, 0.f);
            float v2 = fmaxf(cc[2] + bb0, 0.f), v3 = fmaxf(cc[3] + bb1, 0.f);
            uint32_t hw, lw;
            int byte0 = r0 * RS + col * 2;
            split_pair_h(v0, v1, hw, lw);
            *(uint32_t*)(sm + byte0) = hw;
            *(uint32_t*)(sm + XSZ + byte0) = lw;
            int byte1 = (r0 + 8) * RS + col * 2;
            split_pair_h(v2, v3, hw, lw);
            *(uint32_t*)(sm + byte1) = hw;
            *(uint32_t*)(sm + XSZ + byte1) = lw;
        }
    }
    copy_w_smem(sm, WOFF, w2o, D, D, RS, tid);
    __syncthreads();

    // layer 2
    warp_gemm32<D, NT8>(xh, xl, wh, RS, RS, wm, wn, lane, c);

    // epilogue 2 (register-direct): bias, max, exp, red.v2 scatter
    int rbase = wm * 32 + (lane >> 2);
    int nodes[4][AR];
    bool okr[4];
#pragma unroll
    for (int s = 0; s < 4; s++) {
        int t = t0 + rbase + s * 8;
        okr[s] = t < T;
#pragma unroll
        for (int p = 0; p < AR; p++) nodes[s][p] = okr[s] ? idx[t * AR + p] : 0;
    }
    float m = -3.402823466e38f;
#pragma unroll
    for (int h = 0; h < 2; h++) {
#pragma unroll
        for (int nt = 0; nt < NT8; nt++) {
            int col = wn * ND2 + nt * 8 + (lane & 3) * 2;
            int p = col >> 6, f = col & 63;
            float bb0 = b2s[col], bb1 = b2s[col + 1];
            const float* cc = c + h * NT8 * 4 + nt * 4;
            float v0 = cc[0] + bb0, v1 = cc[1] + bb1;
            float v2 = cc[2] + bb0, v3 = cc[3] + bb1;
            int s0 = h * 2, s1 = h * 2 + 1;
            if (okr[s0]) {
                m = fmaxf(m, fmaxf(v0, v1));
                redv2(&g_expsum[(long long)nodes[s0][p] * 64 + f],
                      __expf(8.f * v0), __expf(8.f * v1));
            }
            if (okr[s1]) {
                m = fmaxf(m, fmaxf(v2, v3));
                redv2(&g_expsum[(long long)nodes[s1][p] * 64 + f],
                      __expf(8.f * v2), __expf(8.f * v3));
            }
        }
    }
#pragma unroll
    for (int s = 16; s > 0; s >>= 1) m = fmaxf(m, __shfl_xor_sync(0xffffffffu, m, s));
    if (lane == 0) wmax[wid] = m;
    __syncthreads();
    if (tid == 0) {
        float bm = wmax[0];
#pragma unroll
        for (int w = 1; w < 8; w++) bm = fmaxf(bm, wmax[w]);
        atomicMaxFloat(&g_maxoff, bm);
    }
}

// --------------------------- K4: update MLP ---------------------------------
// 128 nodes/CTA, warp M=32; out written register-direct.
__global__ void __launch_bounds__(256, 2)
k_update_mma(const float* __restrict__ ns,
             long long w1o, const float* __restrict__ b1,
             long long w2o, const float* __restrict__ b2,
             float* __restrict__ out) {
    constexpr int RS = (128 + 8) * 2;       // 272
    constexpr int XSZ = 128 * RS;           // 34816
    constexpr int WOFF = 2 * XSZ;           // 69632
    constexpr int WSZ = 128 * RS;           // 34816
    constexpr int BOFF = WOFF + WSZ;        // 104448

    extern __shared__ char sm[];
    uint32_t sb = smem_u32(sm);
    uint32_t xh = sb, xl = sb + XSZ, wh = sb + WOFF;
    float* b1s = (float*)(sm + BOFF);
    float* b2s = b1s + 128;

    const int tid = threadIdx.x;
    const int wid = tid >> 5, lane = tid & 31;
    const int wm = wid >> 1, wn = wid & 1;
    const int n0 = blockIdx.x * 128;
    const float eps2 = 1e-16f * __expf(8.f * g_maxoff);

    // gather cat = [1/8*log(eps'+S) | ns] rows -> xs
    for (int e = tid; e < 128 * 32; e += 256) {
        int t = e >> 5, q = e & 31;
        int col = q * 4;
        long long n = n0 + t;
        if (n >= NNODES) n = NNODES - 1;    // clamp (tail rows unused)
        float4 v;
        if (col < 64) {
            float4 s = *(const float4*)(g_expsum + n * 64 + col);
            v = make_float4(0.125f * __logf(eps2 + s.x), 0.125f * __logf(eps2 + s.y),
                            0.125f * __logf(eps2 + s.z), 0.125f * __logf(eps2 + s.w));
        } else {
            v = *(const float4*)(ns + n * 64 + (col - 64));
        }
        uint32_t h0, l0, h1, l1;
        split_pair_h(v.x, v.y, h0, l0);
        split_pair_h(v.z, v.w, h1, l1);
        int byte = t * RS + col * 2;
        *(uint32_t*)(sm + byte) = h0;
        *(uint32_t*)(sm + byte + 4) = h1;
        *(uint32_t*)(sm + XSZ + byte) = l0;
        *(uint32_t*)(sm + XSZ + byte + 4) = l1;
    }
    copy_w_smem(sm, WOFF, w1o, 128, 128, RS, tid);
    if (tid < 128) b1s[tid] = b1[tid];
    if (tid < 64) b2s[tid] = b2[tid];
    __syncthreads();

    float c[64];
    // layer 1: N=128, warp half = 64 -> NT8=8
    warp_gemm32<128, 8>(xh, xl, wh, RS, RS, wm, wn, lane, c);
    __syncthreads();

#pragma unroll
    for (int h = 0; h < 2; h++) {
#pragma unroll
        for (int nt = 0; nt < 8; nt++) {
            int col = wn * 64 + nt * 8 + (lane & 3) * 2;
            float bb0 = b1s[col], bb1 = b1s[col + 1];
            int r0 = wm * 32 + h * 16 + (lane >> 2);
            const float* cc = c + h * 32 + nt * 4;
            float v0 = fmaxf(cc[0] + bb0, 0.f), v1 = fmaxf(cc[1] + bb1, 0.f);
            float v2 = fmaxf(cc[2] + bb0, 0.f), v3 = fmaxf(cc[3] + bb1, 0.f);
            uint32_t hw, lw;
            int byte0 = r0 * RS + col * 2;
            split_pair_h(v0, v1, hw, lw);
            *(uint32_t*)(sm + byte0) = hw;
            *(uint32_t*)(sm + XSZ + byte0) = lw;
            int byte1 = (r0 + 8) * RS + col * 2;
            split_pair_h(v2, v3, hw, lw);
            *(uint32_t*)(sm + byte1) = hw;
            *(uint32_t*)(sm + XSZ + byte1) = lw;
        }
    }
    copy_w_smem(sm, WOFF, w2o, 64, 128, RS, tid);
    __syncthreads();

    // layer 2: N=64, warp half = 32 -> NT8=4
    warp_gemm32<128, 4>(xh, xl, wh, RS, RS, wm, wn, lane, c);

    // epilogue 2: direct f32x2 stores
#pragma unroll
    for (int h = 0; h < 2; h++) {
#pragma unroll
        for (int nt = 0; nt < 4; nt++) {
            int col = wn * 32 + nt * 8 + (lane & 3) * 2;
            float bb0 = b2s[col], bb1 = b2s[col + 1];
            int r0 = wm * 32 + h * 16 + (lane >> 2);
            const float* cc = c + h * 16 + nt * 4;
            long long na = n0 + r0, nb = n0 + r0 + 8;
            if (na < NNODES) {
                float2 v = make_float2(cc[0] + bb0, cc[1] + bb1);
                *(float2*)(out + na * 64 + col) = v;
            }
            if (nb < NNODES) {
                float2 v = make_float2(cc[2] + bb0, cc[3] + bb1);
                *(float2*)(out + nb * 64 + col) = v;
            }
        }
    }
}

// ---------------------------------------------------------------------------
extern "C" void kernel_launch(void* const* d_in, const int* in_sizes, int n_in,
                              void* d_out, int out_size) {
    const float* ns   = (const float*)d_in[0];
    const int*   idx0 = (const int*)d_in[1];
    const int*   idx1 = (const int*)d_in[2];
    const int*   idx2 = (const int*)d_in[3];
    const float* r0w1 = (const float*)d_in[4];
    const float* r0b1 = (const float*)d_in[5];
    const float* r0w2 = (const float*)d_in[6];
    const float* r0b2 = (const float*)d_in[7];
    const float* r1w1 = (const float*)d_in[8];
    const float* r1b1 = (const float*)d_in[9];
    const float* r1w2 = (const float*)d_in[10];
    const float* r1b2 = (const float*)d_in[11];
    const float* r2w1 = (const float*)d_in[12];
    const float* r2b1 = (const float*)d_in[13];
    const float* r2w2 = (const float*)d_in[14];
    const float* r2b2 = (const float*)d_in[15];
    const float* uw1  = (const float*)d_in[16];
    const float* ub1  = (const float*)d_in[17];
    const float* uw2  = (const float*)d_in[18];
    const float* ub2  = (const float*)d_in[19];
    float* out = (float*)d_out;

    const int T01 = 300000, T2 = 200000;

    // weight offsets in g_wh (elements)
    const long long O_R0W1 = 0, O_R0W2 = 16384, O_R1W1 = 32768, O_R1W2 = 49152;
    const long long O_R2W1 = 65536, O_R2W2 = 102400, O_UW1 = 139264, O_UW2 = 155648;

    const int SMA2 = 2 * (128 * 272) + 128 * 272 + 2 * 128 * 4 + 64;   // 105.5KB
    const int SMA3 = 2 * (128 * 400) + 192 * 400 + 2 * 192 * 4 + 64;   // 180.8KB
    const int SMU  = 2 * (128 * 272) + 128 * 272 + 128 * 4 + 64 * 4 + 64;
    cudaFuncSetAttribute((const void*)k_rel_mma<2, 2>, cudaFuncAttributeMaxDynamicSharedMemorySize, SMA2);
    cudaFuncSetAttribute((const void*)k_rel_mma<3, 1>, cudaFuncAttributeMaxDynamicSharedMemorySize, SMA3);
    cudaFuncSetAttribute((const void*)k_update_mma, cudaFuncAttributeMaxDynamicSharedMemorySize, SMU);

    // K-1: precompute fp16 weights
    k_w2h<<<(16384 + 255) / 256, 256>>>(r0w1, O_R0W1, 16384);
    k_w2h<<<(16384 + 255) / 256, 256>>>(r0w2, O_R0W2, 16384);
    k_w2h<<<(16384 + 255) / 256, 256>>>(r1w1, O_R1W1, 16384);
    k_w2h<<<(16384 + 255) / 256, 256>>>(r1w2, O_R1W2, 16384);
    k_w2h<<<(36864 + 255) / 256, 256>>>(r2w1, O_R2W1, 36864);
    k_w2h<<<(36864 + 255) / 256, 256>>>(r2w2, O_R2W2, 36864);
    k_w2h<<<(16384 + 255) / 256, 256>>>(uw1,  O_UW1,  16384);
    k_w2h<<<(8192  + 255) / 256, 256>>>(uw2,  O_UW2,  8192);

    // K0
    {
        long long n4 = (long long)NNODES * 64 / 4;
        k_init<<<(int)((n4 + 255) / 256), 256>>>();
    }

    // K1..K3 (fused MLP + scatter)
    k_rel_mma<2, 2><<<(T01 + 127) / 128, 256, SMA2>>>(ns, idx0, O_R0W1, r0b1, O_R0W2, r0b2, T01);
    k_rel_mma<2, 2><<<(T01 + 127) / 128, 256, SMA2>>>(ns, idx1, O_R1W1, r1b1, O_R1W2, r1b2, T01);
    k_rel_mma<3, 1><<<(T2 + 127) / 128, 256, SMA3>>>(ns, idx2, O_R2W1, r2b1, O_R2W2, r2b2, T2);

    // K4
    k_update_mma<<<(NNODES + 127) / 128, 256, SMU>>>(ns, O_UW1, ub1, O_UW2, ub2, out);
}